// round 16
// baseline (speedup 1.0000x reference)
#include <cuda_runtime.h>

// ---------------- problem constants ----------------
#define PN     8192
#define WD     256
#define HD     256
#define TANXc  0.5f
#define TANYc  0.5f
#define FXc    256.0f
#define FYc    256.0f
#define TSZ    8           // tile size in px
#define NTX    32          // tiles per row
#define NTILE  1024
#define TCAP   1024        // per-tile capacity
#define NSEG   8           // depth segments per pixel
#define NTHR   512         // threads per raster block

typedef unsigned long long u64;

// ---------------- scratch ----------------
__device__ float4 g_d1[PN];              // x, y, A, B
__device__ float4 g_d2[PN];              // C, o, r, g
__device__ float  g_d3[PN];              // b
__device__ float4 g_bb[PN];              // mean2d.x, mean2d.y, ext_x, ext_y
__device__ u64    g_key[PN];             // depth_bits<<32 | idx

// ---------------- preprocess: pure per-gaussian math, NO atomics ----------------
__global__ __launch_bounds__(128) void preprocess_kernel(
    const float* __restrict__ means, const float* __restrict__ cols,
    const float* __restrict__ ops, const float* __restrict__ scales,
    const float* __restrict__ rots, const float* __restrict__ Vm,
    const float* __restrict__ Pr)
{
    int i = blockIdx.x * blockDim.x + threadIdx.x;
    if (i >= PN) return;

    float mx = means[3*i+0], my = means[3*i+1], mz = means[3*i+2];

    float pv0 = mx*Vm[0] + my*Vm[4] + mz*Vm[8]  + Vm[12];
    float pv1 = mx*Vm[1] + my*Vm[5] + mz*Vm[9]  + Vm[13];
    float pv2 = mx*Vm[2] + my*Vm[6] + mz*Vm[10] + Vm[14];

    float ph0 = mx*Pr[0] + my*Pr[4] + mz*Pr[8]  + Pr[12];
    float ph1 = mx*Pr[1] + my*Pr[5] + mz*Pr[9]  + Pr[13];
    float ph3 = mx*Pr[3] + my*Pr[7] + mz*Pr[11] + Pr[15];
    float invw = __fdividef(1.0f, ph3 + 1e-7f);
    float m2x = ((ph0*invw + 1.0f) * (float)WD - 1.0f) * 0.5f;
    float m2y = ((ph1*invw + 1.0f) * (float)HD - 1.0f) * 0.5f;

    float qr = rots[4*i+0], qx = rots[4*i+1], qy = rots[4*i+2], qz = rots[4*i+3];
    float qin = rsqrtf(qr*qr + qx*qx + qy*qy + qz*qz);
    qr *= qin; qx *= qin; qy *= qin; qz *= qin;
    float R[3][3];
    R[0][0] = 1.0f - 2.0f*(qy*qy + qz*qz); R[0][1] = 2.0f*(qx*qy - qr*qz); R[0][2] = 2.0f*(qx*qz + qr*qy);
    R[1][0] = 2.0f*(qx*qy + qr*qz); R[1][1] = 1.0f - 2.0f*(qx*qx + qz*qz); R[1][2] = 2.0f*(qy*qz - qr*qx);
    R[2][0] = 2.0f*(qx*qz - qr*qy); R[2][1] = 2.0f*(qy*qz + qr*qx); R[2][2] = 1.0f - 2.0f*(qx*qx + qy*qy);

    float s0 = scales[3*i+0], s1 = scales[3*i+1], s2 = scales[3*i+2];
    float sq0 = s0*s0, sq1 = s1*s1, sq2 = s2*s2;

    float Sg[3][3];
    #pragma unroll
    for (int r = 0; r < 3; r++)
        #pragma unroll
        for (int c = 0; c < 3; c++)
            Sg[r][c] = R[r][0]*sq0*R[c][0] + R[r][1]*sq1*R[c][1] + R[r][2]*sq2*R[c][2];

    float Mt[3][3], Cc[3][3];
    #pragma unroll
    for (int r = 0; r < 3; r++)
        #pragma unroll
        for (int k = 0; k < 3; k++)
            Mt[r][k] = Vm[0*4+r]*Sg[0][k] + Vm[1*4+r]*Sg[1][k] + Vm[2*4+r]*Sg[2][k];
    #pragma unroll
    for (int r = 0; r < 3; r++)
        #pragma unroll
        for (int l = 0; l < 3; l++)
            Cc[r][l] = Mt[r][0]*Vm[0*4+l] + Mt[r][1]*Vm[1*4+l] + Mt[r][2]*Vm[2*4+l];

    float tz  = pv2;
    float itz = __fdividef(1.0f, tz);
    float limx = 1.3f * TANXc, limy = 1.3f * TANYc;
    float txc = fminf(limx, fmaxf(-limx, pv0*itz)) * tz;
    float tyc = fminf(limy, fmaxf(-limy, pv1*itz)) * tz;
    float J00 = FXc*itz, J02 = -FXc*txc*itz*itz;
    float J11 = FYc*itz, J12 = -FYc*tyc*itz*itz;

    float T00 = J00*Cc[0][0] + J02*Cc[2][0];
    float T01 = J00*Cc[0][1] + J02*Cc[2][1];
    float T02 = J00*Cc[0][2] + J02*Cc[2][2];
    float T11 = J11*Cc[1][1] + J12*Cc[2][1];
    float T12 = J11*Cc[1][2] + J12*Cc[2][2];
    float c00 = T00*J00 + T02*J02;
    float c01 = T01*J11 + T02*J12;
    float c11 = T11*J11 + T12*J12;

    float a = c00 + 0.3f, b = c01, c = c11 + 0.3f;
    float det  = a*c - b*b;
    float idet = __fdividef(1.0f, det);
    float A  = c*idet, B = -b*idet, C2 = a*idet;

    float o   = ops[i];
    float tau = 2.0f * __logf(255.0f * o);
    float tq  = fmaxf(tau, 0.0f);
    float ex  = sqrtf(tq * a) + 1.0f;
    float ey  = sqrtf(tq * c) + 1.0f;
    if (tau <= 0.0f) { ex = -1e30f; ey = -1e30f; }   // never visible

    g_d1[i] = make_float4(m2x, m2y, A, B);
    g_d2[i] = make_float4(C2, o, cols[3*i+0], cols[3*i+1]);
    g_d3[i] = cols[3*i+2];
    g_bb[i] = make_float4(m2x, m2y, ex, ey);
    g_key[i] = ((u64)__float_as_uint(pv2) << 32) | (unsigned)i;   // pv2>0: bit-monotonic
}

// ---------------- fused: per-tile scan + sort + gather-to-smem + 8-segment blend ----------------
// dynamic smem layout: u64 sk[TCAP] | float4 pa[TCAP] | float4 pb[TCAP] | float pc[TCAP]
__global__ __launch_bounds__(NTHR) void raster_kernel(const float* __restrict__ bg,
                                                      float* __restrict__ out)
{
    extern __shared__ char dyn[];
    u64*    sk = (u64*)dyn;                                  //  8 KB
    float4* pa = (float4*)(dyn + TCAP * 8);                  // 16 KB
    float4* pb = (float4*)(dyn + TCAP * 24);                 // 16 KB
    float*  pc = (float*)(dyn + TCAP * 40);                  //  4 KB
    __shared__ float4 s_comb[NSEG - 1][64];
    __shared__ int s_cnt;

    const int t = threadIdx.x;
    const int bx = blockIdx.x, by = blockIdx.y;
    const float xmin = (float)(bx * TSZ), xmax = xmin + (float)(TSZ - 1);
    const float ymin = (float)(by * TSZ), ymax = ymin + (float)(TSZ - 1);

    if (t == 0) s_cnt = 0;
    __syncthreads();

    // ---- scan all gaussians (g_bb L1-resident, shared by blocks on the SM) ----
    for (int base = 0; base < PN; base += NTHR) {
        float4 bb = g_bb[base + t];
        bool hit = (bb.x + bb.z >= xmin) && (bb.x - bb.z <= xmax) &&
                   (bb.y + bb.w >= ymin) && (bb.y - bb.w <= ymax);
        if (hit) {
            int p = atomicAdd(&s_cnt, 1);      // order-agnostic; sort canonicalizes
            if (p < TCAP) sk[p] = g_key[base + t];
        }
    }
    __syncthreads();
    const int n = min(s_cnt, TCAP);

    const int pxi = bx * TSZ + ((t & 63) & (TSZ - 1));
    const int pyi = by * TSZ + ((t & 63) >> 3);
    const int pid = pyi * WD + pxi;

    if (n == 0) {
        if (t < 64) {
            out[pid]           = bg[0];
            out[HD*WD + pid]   = bg[1];
            out[2*HD*WD + pid] = bg[2];
        }
        return;
    }

    // ---- bitonic sort by depth key ----
    int m = 2;
    while (m < n) m <<= 1;
    for (int i = n + t; i < m; i += NTHR) sk[i] = ~0ull;
    __syncthreads();
    for (int k = 2; k <= m; k <<= 1) {
        for (int j = k >> 1; j > 0; j >>= 1) {
            for (int p = t; p < (m >> 1); p += NTHR) {
                int i  = ((p & ~(j - 1)) << 1) | (p & (j - 1));
                bool up = ((i & k) == 0);
                u64 x = sk[i], y = sk[i | j];
                if ((x > y) == up) { sk[i] = y; sk[i | j] = x; }
            }
            __syncthreads();
        }
    }

    // ---- gather payload into smem in depth order ----
    for (int i = t; i < n; i += NTHR) {
        int s = (int)(sk[i] & 0xFFFFFFFFu);
        pa[i] = g_d1[s];
        pb[i] = g_d2[s];
        pc[i] = g_d3[s];
    }
    __syncthreads();

    // ---- 8-segment blend straight from smem ----
    const int seg = t >> 6;          // 0..7
    const int px  = t & 63;
    const float pxf = (float)pxi, pyf = (float)pyi;

    const int cs = (n + NSEG - 1) >> 3;        // entries per segment
    const int segbase = seg * cs;
    const int segend  = min(segbase + cs, n);

    float T = 1.0f;
    float ar = 0.0f, ag = 0.0f, ab = 0.0f;

    if (segbase < segend) {
        // software-pipelined smem reads (broadcast within warp)
        float4 na = pa[segbase];
        float4 nb = pb[segbase];
        float  nc = pc[segbase];
        for (int jj = segbase; jj < segend; jj++) {
            float4 ea = na;
            float4 eb = nb;
            float  ec = nc;
            int j1 = jj + 1;
            if (j1 < segend) { na = pa[j1]; nb = pb[j1]; nc = pc[j1]; }

            float dx = ea.x - pxf;
            float dy = ea.y - pyf;
            float power = -0.5f * (ea.z*dx*dx + eb.x*dy*dy) - ea.w*dx*dy;
            float raw = eb.y * __expf(power);     // unconditional; discarded if power>0
            if (power > 0.0f || raw < (1.0f / 255.0f)) continue;
            float alpha = fminf(0.99f, raw);
            float wgt = alpha * T;
            ar += wgt * eb.z;
            ag += wgt * eb.w;
            ab += wgt * ec;
            T *= (1.0f - alpha);
            if (T < 1e-6f) break;               // remaining contribution < 1e-6
        }
    }

    // ---- combine: back-to-front fold  a = a0 + T0*(a1 + T1*(...)), T = prod ----
    if (seg != 0) s_comb[seg - 1][px] = make_float4(ar, ag, ab, T);
    __syncthreads();
    if (seg == 0) {
        float4 cN = s_comb[NSEG - 2][px];        // segment 7
        float br = cN.x, bgn = cN.y, bb2 = cN.z, bT = cN.w;
        #pragma unroll
        for (int sgi = NSEG - 3; sgi >= 0; sgi--) {   // segments 6..1
            float4 ci = s_comb[sgi][px];
            br  = ci.x + ci.w * br;
            bgn = ci.y + ci.w * bgn;
            bb2 = ci.z + ci.w * bb2;
            bT  = ci.w * bT;
        }
        float Tf = T * bT;
        out[pid]           = ar + T * br  + Tf * bg[0];
        out[HD*WD + pid]   = ag + T * bgn + Tf * bg[1];
        out[2*HD*WD + pid] = ab + T * bb2 + Tf * bg[2];
    }
}

// ---------------- launch ----------------
extern "C" void kernel_launch(void* const* d_in, const int* in_sizes, int n_in,
                              void* d_out, int out_size)
{
    const float* means  = (const float*)d_in[0];
    const float* cols   = (const float*)d_in[1];
    const float* ops    = (const float*)d_in[2];
    const float* scales = (const float*)d_in[3];
    const float* rots   = (const float*)d_in[4];
    const float* bg     = (const float*)d_in[5];
    const float* Vm     = (const float*)d_in[6];
    const float* Pr     = (const float*)d_in[7];
    float* out = (float*)d_out;

    const int dyn_bytes = TCAP * 44;   // 8+16+16+4 KB
    static int configured = 0;
    if (!configured) {
        cudaFuncSetAttribute(raster_kernel,
                             cudaFuncAttributeMaxDynamicSharedMemorySize, dyn_bytes);
        configured = 1;
    }

    preprocess_kernel<<<PN/128, 128>>>(means, cols, ops, scales, rots, Vm, Pr);
    dim3 grid(WD/TSZ, HD/TSZ);
    raster_kernel<<<grid, NTHR, dyn_bytes>>>(bg, out);
}